// round 3
// baseline (speedup 1.0000x reference)
#include <cuda_runtime.h>
#include <cuda_fp16.h>

// DifferentiableCensus: out = (1/9) * sum_{3x3, edge-clamped} sigmoid(neighbor - center)
// x: (16,3,512,512) f32 -> 48 independent 512x512 images.
//
// Round 3: MUFU-bound -> halve MUFU issues with tanh.approx.f16x2 (2 tanh / issue).
//  - sigmoid(d) = 0.5 + 0.5*tanh(d/2); accumulate signed tanh T; out = 0.5 + T/18.
//  - 4 cols x 8 rows register tile, every pixel-pair edge computed once
//    (reverse term = negation). 10 MUFU issues per 4-px row (~2.69/px incl. priming).
//  - diffs and accumulation in f32; only tanh input/output quantized to f16.

static constexpr int H = 512;
static constexpr int W = 512;
static constexpr int ROWS_PER_THREAD = 8;
static constexpr int BLOCK_X = 128;            // 128 threads * 4 cols = 512 cols

__device__ __forceinline__ __half2 tanh_h2(__half2 h) {
    unsigned u = *reinterpret_cast<unsigned*>(&h);
    unsigned r;
    asm("tanh.approx.f16x2 %0, %1;" : "=r"(r) : "r"(u));
    return *reinterpret_cast<__half2*>(&r);
}

// 4 tanh in 2 MUFU issues
__device__ __forceinline__ void tanh4(float d0, float d1, float d2, float d3, float* t) {
    float2 a = __half22float2(tanh_h2(__floats2half2_rn(d0, d1)));
    float2 b = __half22float2(tanh_h2(__floats2half2_rn(d2, d3)));
    t[0] = a.x; t[1] = a.y; t[2] = b.x; t[3] = b.y;
}

// 2 tanh in 1 MUFU issue
__device__ __forceinline__ float2 tanh2(float d0, float d1) {
    return __half22float2(tanh_h2(__floats2half2_rn(d0, d1)));
}

__device__ __forceinline__ void load_row(const float* __restrict__ row,
                                         int c0, int cl, int cr, float v[6]) {
    const float4 m = __ldg(reinterpret_cast<const float4*>(row + c0));
    v[0] = 0.5f * __ldg(row + cl);
    v[1] = 0.5f * m.x;
    v[2] = 0.5f * m.y;
    v[3] = 0.5f * m.z;
    v[4] = 0.5f * m.w;
    v[5] = 0.5f * __ldg(row + cr);
}

__global__ __launch_bounds__(BLOCK_X)
void census_kernel(const float* __restrict__ x, float* __restrict__ out) {
    const int c0  = threadIdx.x * 4;
    const int r0  = blockIdx.y * ROWS_PER_THREAD;
    const int img = blockIdx.z;

    const float* __restrict__ xi = x   + (size_t)img * H * W;
    float* __restrict__       oi = out + (size_t)img * H * W;

    const int cl = max(c0 - 1, 0);
    const int cr = min(c0 + 4, W - 1);

    float p[6], b[6];                                  // rows r-1, r (prescaled 0.5)
    load_row(xi + (size_t)max(r0 - 1, 0) * W, c0, cl, cr, p);
    load_row(xi + (size_t)r0 * W,             c0, cl, cr, b);

    // Priming carries: S / SE / SW edge tanh of row r0-1 (r0==0 -> 0 == sigmoid(0)).
    float pS[4], pDR[4], pDL[4];
    tanh4(b[1] - p[1], b[2] - p[2], b[3] - p[3], b[4] - p[4], pS);
    tanh4(b[2] - p[1], b[3] - p[2], b[4] - p[3], b[5] - p[4], pDR);
    tanh4(b[0] - p[1], b[1] - p[2], b[2] - p[3], b[3] - p[4], pDL);

    #pragma unroll
    for (int k = 0; k < ROWS_PER_THREAD; k++) {
        const int r = r0 + k;
        float n[6];
        load_row(xi + (size_t)min(r + 1, H - 1) * W, c0, cl, cr, n);

        float tS[4], tDR[4], tDL[4], tE[4];
        tanh4(n[1] - b[1], n[2] - b[2], n[3] - b[3], n[4] - b[4], tS);   // S
        tanh4(n[2] - b[1], n[3] - b[2], n[4] - b[3], n[5] - b[4], tDR);  // SE
        tanh4(n[0] - b[1], n[1] - b[2], n[2] - b[3], n[3] - b[4], tDL);  // SW
        tanh4(b[2] - b[1], b[3] - b[2], b[4] - b[3], b[5] - b[4], tE);   // E

        const float2 h1 = tanh2(b[0] - b[1], p[0] - b[1]);               // W0, NW0
        const float2 h2 = tanh2(p[5] - b[4], 0.0f);                      // NE3
        const float tW0 = h1.x, tUL0 = h1.y, tUR3 = h2.x;

        // Signed sums: forward edges +, reverse of previously computed edges -.
        const float T0 = (tS[0] + tDR[0]) + (tDL[0] - pS[0])
                       + (tE[0] + tW0)    + (tUL0   - pDL[1]);
        const float T1 = (tS[1] + tDR[1]) + (tDL[1] - pS[1])
                       + (tE[1] - tE[0])  - (pDR[0] + pDL[2]);
        const float T2 = (tS[2] + tDR[2]) + (tDL[2] - pS[2])
                       + (tE[2] - tE[1])  - (pDR[1] + pDL[3]);
        const float T3 = (tS[3] + tDR[3]) + (tDL[3] - pS[3])
                       + (tE[3] - tE[2])  + (tUR3   - pDR[2]);

        float4 o;
        o.x = fmaf(T0, 1.0f / 18.0f, 0.5f);
        o.y = fmaf(T1, 1.0f / 18.0f, 0.5f);
        o.z = fmaf(T2, 1.0f / 18.0f, 0.5f);
        o.w = fmaf(T3, 1.0f / 18.0f, 0.5f);
        *reinterpret_cast<float4*>(oi + (size_t)r * W + c0) = o;

        #pragma unroll
        for (int i = 0; i < 6; i++) { p[i] = b[i]; b[i] = n[i]; }
        #pragma unroll
        for (int i = 0; i < 4; i++) { pS[i] = tS[i]; pDR[i] = tDR[i]; pDL[i] = tDL[i]; }
    }
}

extern "C" void kernel_launch(void* const* d_in, const int* in_sizes, int n_in,
                              void* d_out, int out_size) {
    (void)in_sizes; (void)n_in; (void)out_size;
    const float* x = (const float*)d_in[0];
    float* out = (float*)d_out;

    dim3 block(BLOCK_X, 1, 1);
    dim3 grid(1, H / ROWS_PER_THREAD, 16 * 3);
    census_kernel<<<grid, block>>>(x, out);
}